// round 16
// baseline (speedup 1.0000x reference)
#include <cuda_runtime.h>
#include <cuda_fp16.h>
#include <cstdint>

#define DI      8192
#define DO      8192
#define NB      1024
#define FAN     16
#define NNZ     (DI * FAN)          // 131072
#define BT      8                   // batch rows per CTA tile (8 halves = 16B)
#define NBT     (NB / BT)           // 128 batch tiles
#define JCHUNK  512                 // j's per fine work unit (1 per thread)
#define NJC     (DO / JCHUNK)       // 16 j-chunks per btile
#define UNITS   (NBT * NJC)         // 2048 fine units
#define THREADS 512
#define SMEM_BYTES (DI * 16)        // 8192 slots x 16B = 128 KB

// Scratch (no allocation allowed): fixed-degree index table.
// g_idx[j*16 + s] = swizzled slot index of the s-th edge into output j.
__device__ __align__(16) unsigned short g_idx[DO * FAN];
// Modular slot counter: each launch adds exactly FAN per j, so
// (atomicAdd & 15) enumerates slots 0..15 uniquely per launch — NO reset pass.
__device__ unsigned g_cnt[DO];
// Grid-barrier ticket counter. Each launch adds exactly ncta arrivals, so
// target = (ticket/ncta + 1)*ncta self-aligns across graph replays — NO reset.
__device__ unsigned g_bar;

__device__ __forceinline__ unsigned swz(unsigned i) {
    // XOR swizzle on 16B slot index: staging stores conflict-free.
    return i ^ ((i >> 3) & 7u);
}

__device__ __forceinline__ unsigned h2bits(__half2 h) {
    return *reinterpret_cast<unsigned*>(&h);
}
__device__ __forceinline__ __half2 bits2h(unsigned u) {
    return *reinterpret_cast<__half2*>(&u);
}

// Stage 8 batch rows as fp16 (scaled by 100), transposed + swizzled.
__device__ __forceinline__ void stage_tile(uint4* xs, const float* __restrict__ x,
                                           int b0) {
    const float4* r[BT];
    #pragma unroll
    for (int q = 0; q < BT; ++q)
        r[q] = reinterpret_cast<const float4*>(x + (size_t)(b0 + q) * DI);

    #pragma unroll
    for (int t = threadIdx.x; t < DI / 4; t += THREADS) {
        float4 v[BT];
        #pragma unroll
        for (int q = 0; q < BT; ++q) v[q] = r[q][t];
        unsigned i = (unsigned)t * 4u;
        #pragma unroll
        for (int c = 0; c < 4; ++c) {
            float e[BT];
            e[0] = (&v[0].x)[c]; e[1] = (&v[1].x)[c];
            e[2] = (&v[2].x)[c]; e[3] = (&v[3].x)[c];
            e[4] = (&v[4].x)[c]; e[5] = (&v[5].x)[c];
            e[6] = (&v[6].x)[c]; e[7] = (&v[7].x)[c];
            uint4 o;
            o.x = h2bits(__float22half2_rn(make_float2(100.f*e[0], 100.f*e[1])));
            o.y = h2bits(__float22half2_rn(make_float2(100.f*e[2], 100.f*e[3])));
            o.z = h2bits(__float22half2_rn(make_float2(100.f*e[4], 100.f*e[5])));
            o.w = h2bits(__float22half2_rn(make_float2(100.f*e[6], 100.f*e[7])));
            xs[swz(i + c)] = o;
        }
    }
}

__global__ void __launch_bounds__(THREADS, 1)
fused_kernel(const float* __restrict__ x, float* __restrict__ y,
             const int* __restrict__ pre, const int* __restrict__ post,
             int ncta) {
    extern __shared__ uint4 xs[];   // xs[swz(i)] = fp16 {100*x[b0..b7][i]}
    __shared__ unsigned bar_target;

    // ---- Phase 1: build the index table. 4 edges per active thread via
    //      coalesced int4 loads (measured-fastest build shape, R13):
    //      one iteration, no ragged second pass. ----
    {
        int gtid = blockIdx.x * THREADS + threadIdx.x;
        if (gtid < NNZ / 4) {
            int e0 = gtid * 4;
            int4 jj = *reinterpret_cast<const int4*>(post + e0);
            int4 ii = *reinterpret_cast<const int4*>(pre + e0);
            int j[4] = {jj.x, jj.y, jj.z, jj.w};
            int i[4] = {ii.x, ii.y, ii.z, ii.w};
            #pragma unroll
            for (int k = 0; k < 4; ++k) {
                unsigned s = atomicAdd(&g_cnt[j[k]], 1u) & 15u;
                g_idx[j[k] * FAN + s] = (unsigned short)swz((unsigned)i[k]);
            }
        }
    }

    // ---- Phase 2: ARRIVE FIRST (release my g_idx writes), THEN stage the
    //      first tile into the barrier-wait shadow. ----
    __threadfence();                 // release: g_idx/g_cnt visible before arrive
    __syncthreads();                 // whole CTA's build done
    if (threadIdx.x == 0) {
        unsigned t = atomicAdd(&g_bar, 1u);
        bar_target = (t / (unsigned)ncta + 1u) * (unsigned)ncta;
    }

    int u0 = (int)(((long long)blockIdx.x       * UNITS) / ncta);
    int u1 = (int)(((long long)(blockIdx.x + 1) * UNITS) / ncta);

    int b_first = u0 >> 4;          // NJC = 16
    stage_tile(xs, x, b_first * BT);  // overlaps other CTAs' build tails
    __syncthreads();                  // staging done; bar_target visible

    // ---- Phase 3: wait for all builds (read-only acquire polls, no atomics) ----
    if (threadIdx.x == 0) {
        unsigned tgt = bar_target;
        unsigned v;
        for (;;) {
            asm volatile("ld.global.acquire.gpu.u32 %0, [%1];"
                         : "=r"(v) : "l"(&g_bar));
            if (v >= tgt) break;
            __nanosleep(64);
        }
    }
    __syncthreads();                 // all CTAs' g_idx now safe to read

    const uint4* idx4 = reinterpret_cast<const uint4*>(g_idx);

    int jfirst = (u0 & 15) * JCHUNK + threadIdx.x;
    uint4 A = idx4[2 * jfirst];
    uint4 B = idx4[2 * jfirst + 1];

    int curb = b_first;
    for (int u = u0; u < u1; ++u) {
        int b  = u >> 4;
        int jc = u & 15;
        int b0 = b * BT;

        if (b != curb) {
            __syncthreads();         // everyone done with old tile
            stage_tile(xs, x, b0);
            __syncthreads();
            curb = b;
        }

        // ---- Prefetch next unit's indices across this unit's gather ----
        int un = u + 1;
        uint4 An = A, Bn = B;
        if (un < u1) {
            int jn = (un & 15) * JCHUNK + threadIdx.x;
            An = idx4[2 * jn];
            Bn = idx4[2 * jn + 1];
        }

        int j = jc * JCHUNK + threadIdx.x;

        unsigned s[16];
        s[0]  = A.x & 0xFFFFu;  s[1]  = A.x >> 16;
        s[2]  = A.y & 0xFFFFu;  s[3]  = A.y >> 16;
        s[4]  = A.z & 0xFFFFu;  s[5]  = A.z >> 16;
        s[6]  = A.w & 0xFFFFu;  s[7]  = A.w >> 16;
        s[8]  = B.x & 0xFFFFu;  s[9]  = B.x >> 16;
        s[10] = B.y & 0xFFFFu;  s[11] = B.y >> 16;
        s[12] = B.z & 0xFFFFu;  s[13] = B.z >> 16;
        s[14] = B.w & 0xFFFFu;  s[15] = B.w >> 16;

        // Front-batch ALL 16 LDS.128 before any arithmetic -> MLP ~16.
        uint4 v[16];
        #pragma unroll
        for (int w = 0; w < 16; ++w) v[w] = xs[s[w]];

        float a0=0.f,a1=0.f,a2=0.f,a3=0.f,a4=0.f,a5=0.f,a6=0.f,a7=0.f;

        #pragma unroll
        for (int p = 0; p < 8; ++p) {
            uint4 va = v[2*p];
            uint4 vb = v[2*p + 1];
            __half2 h0 = __hadd2(bits2h(va.x), bits2h(vb.x));
            __half2 h1 = __hadd2(bits2h(va.y), bits2h(vb.y));
            __half2 h2 = __hadd2(bits2h(va.z), bits2h(vb.z));
            __half2 h3 = __hadd2(bits2h(va.w), bits2h(vb.w));
            float2 f0 = __half22float2(h0);
            float2 f1 = __half22float2(h1);
            float2 f2 = __half22float2(h2);
            float2 f3 = __half22float2(h3);
            a0 += f0.x; a1 += f0.y; a2 += f1.x; a3 += f1.y;
            a4 += f2.x; a5 += f2.y; a6 += f3.x; a7 += f3.y;
        }

        y[(size_t)(b0 + 0) * DO + j] = a0;
        y[(size_t)(b0 + 1) * DO + j] = a1;
        y[(size_t)(b0 + 2) * DO + j] = a2;
        y[(size_t)(b0 + 3) * DO + j] = a3;
        y[(size_t)(b0 + 4) * DO + j] = a4;
        y[(size_t)(b0 + 5) * DO + j] = a5;
        y[(size_t)(b0 + 6) * DO + j] = a6;
        y[(size_t)(b0 + 7) * DO + j] = a7;

        A = An; B = Bn;
    }
}

extern "C" void kernel_launch(void* const* d_in, const int* in_sizes, int n_in,
                              void* d_out, int out_size) {
    const float* x    = (const float*)d_in[0];
    const int*   pre  = (const int*)d_in[1];
    const int*   post = (const int*)d_in[2];
    float*       y    = (float*)d_out;

    (void)in_sizes; (void)n_in; (void)out_size;

    int nsm = 0;
    cudaDeviceGetAttribute(&nsm, cudaDevAttrMultiProcessorCount, 0);
    if (nsm <= 0) nsm = 148;

    cudaFuncSetAttribute(fused_kernel,
                         cudaFuncAttributeMaxDynamicSharedMemorySize, SMEM_BYTES);

    // Single fused launch: grid = #SMs guarantees all CTAs co-resident
    // (128 KB smem -> 1 CTA/SM), so the in-kernel grid barrier is safe.
    fused_kernel<<<nsm, THREADS, SMEM_BYTES>>>(x, y, pre, post, nsm);
}

// round 17
// speedup vs baseline: 1.0535x; 1.0535x over previous
#include <cuda_runtime.h>
#include <cuda_fp16.h>
#include <cstdint>

#define DI      8192
#define DO      8192
#define NB      1024
#define FAN     16
#define NNZ     (DI * FAN)          // 131072
#define NG      (NNZ / 4)           // 32768 int4 edge-groups
#define BT      8                   // batch rows per CTA tile (8 halves = 16B)
#define NBT     (NB / BT)           // 128 batch tiles
#define JCHUNK  512                 // j's per fine work unit (1 per thread)
#define NJC     (DO / JCHUNK)       // 16 j-chunks per btile
#define UNITS   (NBT * NJC)         // 2048 fine units
#define THREADS 512
#define SMEM_BYTES (DI * 16)        // 8192 slots x 16B = 128 KB

// Scratch (no allocation allowed): fixed-degree index table.
// g_idx[j*16 + s] = swizzled slot index of the s-th edge into output j.
__device__ __align__(16) unsigned short g_idx[DO * FAN];
// Modular slot counter: each launch adds exactly FAN per j, so
// (atomicAdd & 15) enumerates slots 0..15 uniquely per launch — NO reset pass.
__device__ unsigned g_cnt[DO];
// Grid-barrier ticket counter. Each launch adds exactly ncta arrivals, so
// target = (ticket/ncta + 1)*ncta self-aligns across graph replays — NO reset.
__device__ unsigned g_bar;

__device__ __forceinline__ unsigned swz(unsigned i) {
    // XOR swizzle on 16B slot index: staging stores conflict-free.
    return i ^ ((i >> 3) & 7u);
}

__device__ __forceinline__ unsigned h2bits(__half2 h) {
    return *reinterpret_cast<unsigned*>(&h);
}
__device__ __forceinline__ __half2 bits2h(unsigned u) {
    return *reinterpret_cast<__half2*>(&u);
}

// Stage 8 batch rows as fp16 (scaled by 100), transposed + swizzled.
__device__ __forceinline__ void stage_tile(uint4* xs, const float* __restrict__ x,
                                           int b0) {
    const float4* r[BT];
    #pragma unroll
    for (int q = 0; q < BT; ++q)
        r[q] = reinterpret_cast<const float4*>(x + (size_t)(b0 + q) * DI);

    #pragma unroll
    for (int t = threadIdx.x; t < DI / 4; t += THREADS) {
        float4 v[BT];
        #pragma unroll
        for (int q = 0; q < BT; ++q) v[q] = r[q][t];
        unsigned i = (unsigned)t * 4u;
        #pragma unroll
        for (int c = 0; c < 4; ++c) {
            float e[BT];
            e[0] = (&v[0].x)[c]; e[1] = (&v[1].x)[c];
            e[2] = (&v[2].x)[c]; e[3] = (&v[3].x)[c];
            e[4] = (&v[4].x)[c]; e[5] = (&v[5].x)[c];
            e[6] = (&v[6].x)[c]; e[7] = (&v[7].x)[c];
            uint4 o;
            o.x = h2bits(__float22half2_rn(make_float2(100.f*e[0], 100.f*e[1])));
            o.y = h2bits(__float22half2_rn(make_float2(100.f*e[2], 100.f*e[3])));
            o.z = h2bits(__float22half2_rn(make_float2(100.f*e[4], 100.f*e[5])));
            o.w = h2bits(__float22half2_rn(make_float2(100.f*e[6], 100.f*e[7])));
            xs[swz(i + c)] = o;
        }
    }
}

__global__ void __launch_bounds__(THREADS, 1)
fused_kernel(const float* __restrict__ x, float* __restrict__ y,
             const int* __restrict__ pre, const int* __restrict__ post,
             int ncta) {
    extern __shared__ uint4 xs[];   // xs[swz(i)] = fp16 {100*x[b0..b7][i]}
    __shared__ unsigned bar_target;

    // ---- Phase 1: build the index table. Int4-coalesced AND balanced:
    //      each CTA takes a contiguous slice of ~NG/ncta groups (1/thread).
    //      Balance across CTAs dominates (barrier releases at the max CTA);
    //      R16's compact layout put all work on 64/152 CTAs and regressed. ----
    {
        int g0 = (int)(((long long)blockIdx.x       * NG) / ncta);
        int g1 = (int)(((long long)(blockIdx.x + 1) * NG) / ncta);
        int g  = g0 + threadIdx.x;
        if (g < g1) {
            int e0 = g * 4;
            int4 jj = *reinterpret_cast<const int4*>(post + e0);
            int4 ii = *reinterpret_cast<const int4*>(pre + e0);
            int j[4] = {jj.x, jj.y, jj.z, jj.w};
            int i[4] = {ii.x, ii.y, ii.z, ii.w};
            #pragma unroll
            for (int k = 0; k < 4; ++k) {
                unsigned s = atomicAdd(&g_cnt[j[k]], 1u) & 15u;
                g_idx[j[k] * FAN + s] = (unsigned short)swz((unsigned)i[k]);
            }
        }
    }

    // ---- Phase 2: ARRIVE FIRST (release my g_idx writes), THEN stage the
    //      first tile into the barrier-wait shadow. ----
    __threadfence();                 // release: g_idx/g_cnt visible before arrive
    __syncthreads();                 // whole CTA's build done
    if (threadIdx.x == 0) {
        unsigned t = atomicAdd(&g_bar, 1u);
        bar_target = (t / (unsigned)ncta + 1u) * (unsigned)ncta;
    }

    int u0 = (int)(((long long)blockIdx.x       * UNITS) / ncta);
    int u1 = (int)(((long long)(blockIdx.x + 1) * UNITS) / ncta);

    int b_first = u0 >> 4;          // NJC = 16
    stage_tile(xs, x, b_first * BT);  // overlaps other CTAs' build tails
    __syncthreads();                  // staging done; bar_target visible

    // ---- Phase 3: wait for all builds (read-only acquire polls, no atomics) ----
    if (threadIdx.x == 0) {
        unsigned tgt = bar_target;
        unsigned v;
        for (;;) {
            asm volatile("ld.global.acquire.gpu.u32 %0, [%1];"
                         : "=r"(v) : "l"(&g_bar));
            if (v >= tgt) break;
            __nanosleep(64);
        }
    }
    __syncthreads();                 // all CTAs' g_idx now safe to read

    const uint4* idx4 = reinterpret_cast<const uint4*>(g_idx);

    int jfirst = (u0 & 15) * JCHUNK + threadIdx.x;
    uint4 A = idx4[2 * jfirst];
    uint4 B = idx4[2 * jfirst + 1];

    int curb = b_first;
    for (int u = u0; u < u1; ++u) {
        int b  = u >> 4;
        int jc = u & 15;
        int b0 = b * BT;

        if (b != curb) {
            __syncthreads();         // everyone done with old tile
            stage_tile(xs, x, b0);
            __syncthreads();
            curb = b;
        }

        // ---- Prefetch next unit's indices across this unit's gather ----
        int un = u + 1;
        uint4 An = A, Bn = B;
        if (un < u1) {
            int jn = (un & 15) * JCHUNK + threadIdx.x;
            An = idx4[2 * jn];
            Bn = idx4[2 * jn + 1];
        }

        int j = jc * JCHUNK + threadIdx.x;

        unsigned s[16];
        s[0]  = A.x & 0xFFFFu;  s[1]  = A.x >> 16;
        s[2]  = A.y & 0xFFFFu;  s[3]  = A.y >> 16;
        s[4]  = A.z & 0xFFFFu;  s[5]  = A.z >> 16;
        s[6]  = A.w & 0xFFFFu;  s[7]  = A.w >> 16;
        s[8]  = B.x & 0xFFFFu;  s[9]  = B.x >> 16;
        s[10] = B.y & 0xFFFFu;  s[11] = B.y >> 16;
        s[12] = B.z & 0xFFFFu;  s[13] = B.z >> 16;
        s[14] = B.w & 0xFFFFu;  s[15] = B.w >> 16;

        // Front-batch ALL 16 LDS.128 before any arithmetic -> MLP ~16.
        uint4 v[16];
        #pragma unroll
        for (int w = 0; w < 16; ++w) v[w] = xs[s[w]];

        float a0=0.f,a1=0.f,a2=0.f,a3=0.f,a4=0.f,a5=0.f,a6=0.f,a7=0.f;

        #pragma unroll
        for (int p = 0; p < 8; ++p) {
            uint4 va = v[2*p];
            uint4 vb = v[2*p + 1];
            __half2 h0 = __hadd2(bits2h(va.x), bits2h(vb.x));
            __half2 h1 = __hadd2(bits2h(va.y), bits2h(vb.y));
            __half2 h2 = __hadd2(bits2h(va.z), bits2h(vb.z));
            __half2 h3 = __hadd2(bits2h(va.w), bits2h(vb.w));
            float2 f0 = __half22float2(h0);
            float2 f1 = __half22float2(h1);
            float2 f2 = __half22float2(h2);
            float2 f3 = __half22float2(h3);
            a0 += f0.x; a1 += f0.y; a2 += f1.x; a3 += f1.y;
            a4 += f2.x; a5 += f2.y; a6 += f3.x; a7 += f3.y;
        }

        y[(size_t)(b0 + 0) * DO + j] = a0;
        y[(size_t)(b0 + 1) * DO + j] = a1;
        y[(size_t)(b0 + 2) * DO + j] = a2;
        y[(size_t)(b0 + 3) * DO + j] = a3;
        y[(size_t)(b0 + 4) * DO + j] = a4;
        y[(size_t)(b0 + 5) * DO + j] = a5;
        y[(size_t)(b0 + 6) * DO + j] = a6;
        y[(size_t)(b0 + 7) * DO + j] = a7;

        A = An; B = Bn;
    }
}

extern "C" void kernel_launch(void* const* d_in, const int* in_sizes, int n_in,
                              void* d_out, int out_size) {
    const float* x    = (const float*)d_in[0];
    const int*   pre  = (const int*)d_in[1];
    const int*   post = (const int*)d_in[2];
    float*       y    = (float*)d_out;

    (void)in_sizes; (void)n_in; (void)out_size;

    int nsm = 0;
    cudaDeviceGetAttribute(&nsm, cudaDevAttrMultiProcessorCount, 0);
    if (nsm <= 0) nsm = 148;

    cudaFuncSetAttribute(fused_kernel,
                         cudaFuncAttributeMaxDynamicSharedMemorySize, SMEM_BYTES);

    // Single fused launch: grid = #SMs guarantees all CTAs co-resident
    // (128 KB smem -> 1 CTA/SM), so the in-kernel grid barrier is safe.
    fused_kernel<<<nsm, THREADS, SMEM_BYTES>>>(x, y, pre, post, nsm);
}